// round 4
// baseline (speedup 1.0000x reference)
#include <cuda_runtime.h>

// MaxPool 2x2 stride 2, (16,64,512,512) fp32 -> (16,64,256,256) fp32.
// DRAM-roofline streaming kernel. One warp owns one full input row PAIR
// (2 x 2KB): each lane issues 8 front-batched, perfectly coalesced LDG.128
// (every warp wavefront = 4 fully-used 128B lines), pools vertically+
// horizontally, and writes one full 1KB output row via 4 coalesced STG.64.
// MLP=8 per thread with zero coalescing loss.

#define IN_H 512
#define OUT_H 256
#define BC (16 * 64)

#define IN_ROW_F4 128    // 512 floats / 4
#define OUT_ROW_F2 128   // 256 floats / 2

__global__ void maxpool2x2_kernel(const float4* __restrict__ in4,
                                  float2* __restrict__ out2) {
    unsigned tid  = blockIdx.x * blockDim.x + threadIdx.x;
    unsigned lane = tid & 31;
    unsigned wrp  = tid >> 5;               // global warp id = row-pair id

    unsigned rp = wrp & (OUT_H - 1);        // output row [0,256)
    unsigned bc = wrp >> 8;                 // plane [0,1024)

    unsigned ibase = bc * (IN_H * IN_ROW_F4) + (rp * 2) * IN_ROW_F4 + lane;

    // Front-batch all 8 loads: full row0 + row1, coalesced 512B wavefronts.
    float4 r0a = in4[ibase +  0];
    float4 r0b = in4[ibase + 32];
    float4 r0c = in4[ibase + 64];
    float4 r0d = in4[ibase + 96];
    float4 r1a = in4[ibase + IN_ROW_F4 +  0];
    float4 r1b = in4[ibase + IN_ROW_F4 + 32];
    float4 r1c = in4[ibase + IN_ROW_F4 + 64];
    float4 r1d = in4[ibase + IN_ROW_F4 + 96];

    float2 oa, ob, oc, od;
    oa.x = fmaxf(fmaxf(r0a.x, r0a.y), fmaxf(r1a.x, r1a.y));
    oa.y = fmaxf(fmaxf(r0a.z, r0a.w), fmaxf(r1a.z, r1a.w));
    ob.x = fmaxf(fmaxf(r0b.x, r0b.y), fmaxf(r1b.x, r1b.y));
    ob.y = fmaxf(fmaxf(r0b.z, r0b.w), fmaxf(r1b.z, r1b.w));
    oc.x = fmaxf(fmaxf(r0c.x, r0c.y), fmaxf(r1c.x, r1c.y));
    oc.y = fmaxf(fmaxf(r0c.z, r0c.w), fmaxf(r1c.z, r1c.w));
    od.x = fmaxf(fmaxf(r0d.x, r0d.y), fmaxf(r1d.x, r1d.y));
    od.y = fmaxf(fmaxf(r0d.z, r0d.w), fmaxf(r1d.z, r1d.w));

    unsigned obase = bc * (OUT_H * OUT_ROW_F2) + rp * OUT_ROW_F2 + lane;
    __stcs(&out2[obase +  0], oa);
    __stcs(&out2[obase + 32], ob);
    __stcs(&out2[obase + 64], oc);
    __stcs(&out2[obase + 96], od);
}

extern "C" void kernel_launch(void* const* d_in, const int* in_sizes, int n_in,
                              void* d_out, int out_size) {
    const float4* in4 = (const float4*)d_in[0];
    float2* out2 = (float2*)d_out;

    // one warp per row pair: 1024 planes * 256 row pairs = 262,144 warps
    const unsigned total_threads = (unsigned)BC * OUT_H * 32;  // 8,388,608
    const int threads = 256;
    const unsigned blocks = total_threads / threads;           // 32,768

    maxpool2x2_kernel<<<blocks, threads>>>(in4, out2);
}